// round 2
// baseline (speedup 1.0000x reference)
#include <cuda_runtime.h>
#include <math.h>

// ---------------- problem constants ----------------
#define T_LEN  8820     // BLOCK_NUM
#define BATCH  64
#define POOLW  10
#define NCHUNK 32
#define CHUNK  ((T_LEN + NCHUNK - 1) / NCHUNK)   // 276
#define TILE   64
#define NST    32       // d_inner(2) * d_state(16)
#define NCH    256      // mlp output channels
#define TR     84       // t-tile for output kernel; 8820 = 84*105

// ---------------- device scratch (no allocations allowed) ----------------
__device__ float g_pooled[BATCH * T_LEN];
__device__ float g_final [2 * BATCH * T_LEN];          // [dir][b][t] (original time)
__device__ float g_hend  [128 * NCHUNK * NST];
__device__ float g_aprod [128 * NCHUNK * NST];
__device__ float g_hinit [128 * NCHUNK * NST];

// ---------------- helpers ----------------
__device__ __forceinline__ float siluf(float x) {
    return __fdividef(x, 1.0f + __expf(-x));
}
__device__ __forceinline__ float softplusf(float x) {
    return (x > 20.0f) ? x : log1pf(__expf(x));
}

// ---------------- kernel 1: max pool ----------------
__global__ __launch_bounds__(256) void pool_kernel(const float* __restrict__ x) {
    int idx = blockIdx.x * blockDim.x + threadIdx.x;
    if (idx >= BATCH * T_LEN) return;
    const float* p = x + (long)idx * POOLW;
    float m = p[0];
#pragma unroll
    for (int j = 1; j < POOLW; j++) m = fmaxf(m, p[j]);
    g_pooled[idx] = m;
}

// ---------------- kernels 2/4: chunked selective scan ----------------
// grid = (NCHUNK, 128 chains), block = TILE threads.
// Phase A (all threads): per-timestep coefficients (a, b[, c]) -> smem.
// Phase B (warp 0):      serial recurrence h = a*h + b, lane = state.
//                        PASS2: in-place sc[idx] *= h (value for reduction).
// Phase C (PASS2):       deferred reduction sum_lane(sc) + r -> g_final.
template <bool PASS2>
__global__ __launch_bounds__(TILE) void scan_kernel(
    const float* __restrict__ in_w,  // (2,1,4)
    const float* __restrict__ cw,    // (2,2,4)
    const float* __restrict__ cb,    // (2,2)
    const float* __restrict__ xpw,   // (2,2,33)
    const float* __restrict__ dtw,   // (2,1,2)
    const float* __restrict__ dtb,   // (2,2)
    const float* __restrict__ alog,  // (2,2,16)
    const float* __restrict__ dssm,  // (2,2)
    const float* __restrict__ ow)    // (2,2,1)
{
    __shared__ float sa[TILE * 33], sb[TILE * 33];
    __shared__ float sc[PASS2 ? TILE * 33 : 1];      // PASS2 only
    __shared__ float sr[TILE];
    __shared__ float s_inwx[2], s_inwz[2], s_cw[8], s_cb[2];
    __shared__ float s_xpw[66], s_dtw[2], s_dtb[2], s_An[32], s_Dp[2], s_ow[2];

    const int chain = blockIdx.y;
    const int d = chain >> 6, b = chain & 63;
    const int chunk = blockIdx.x;
    const int c0 = chunk * CHUNK;
    const int c1 = min(T_LEN, c0 + CHUNK);
    const int tid = threadIdx.x;

    // stage per-direction weights into smem
    if (tid < 2) {
        s_inwx[tid] = in_w[d * 4 + tid];
        s_inwz[tid] = in_w[d * 4 + 2 + tid];
        s_cb[tid]   = cb [d * 2 + tid];
        s_dtw[tid]  = dtw[d * 2 + tid];
        s_dtb[tid]  = dtb[d * 2 + tid];
        s_Dp[tid]   = dssm[d * 2 + tid];
        s_ow[tid]   = ow [d * 2 + tid];
    }
    if (tid < 8)  s_cw[tid] = cw[d * 8 + tid];
    if (tid < 32) s_An[tid] = -__expf(alog[d * 32 + tid]);   // A = -exp(A_log)
    for (int k = tid; k < 66; k += TILE) s_xpw[k] = xpw[d * 66 + k];
    __syncthreads();

    float h = 0.0f, P = 1.0f;
    if (PASS2 && tid < 32) h = g_hinit[(chain * NCHUNK + chunk) * NST + tid];

    for (int tb = c0; tb < c1; tb += TILE) {
        const int tn = min(TILE, c1 - tb);

        // ---- phase A: parallel per-timestep precompute ----
        if (tid < tn) {
            const int l = tb + tid;      // position in direction frame
            float u[4];
#pragma unroll
            for (int k = 0; k < 4; k++) {
                int lk = l - 3 + k;
                u[k] = (lk >= 0) ? g_pooled[b * T_LEN + (d ? (T_LEN - 1 - lk) : lk)] : 0.0f;
            }
            float xc[2], dtv[2], g2[2], w2[2];
#pragma unroll
            for (int i = 0; i < 2; i++) {
                float cv = s_cw[i * 4 + 0] * u[0] + s_cw[i * 4 + 1] * u[1]
                         + s_cw[i * 4 + 2] * u[2] + s_cw[i * 4 + 3] * u[3];
                cv = s_cb[i] + s_inwx[i] * cv;     // causal conv (k=4) folded through in_proj
                xc[i] = siluf(cv);
            }
            float dtr = xc[0] * s_xpw[0] + xc[1] * s_xpw[33];
#pragma unroll
            for (int i = 0; i < 2; i++) {
                dtv[i] = softplusf(dtr * s_dtw[i] + s_dtb[i]);
                g2[i]  = dtv[i] * xc[i];
            }
            if (PASS2) {
                float r = u[3];                     // residual (pooled value)
#pragma unroll
                for (int i = 0; i < 2; i++) {
                    float z = u[3] * s_inwz[i];
                    w2[i] = siluf(z) * s_ow[i];     // gate * out_proj weight
                    r += w2[i] * xc[i] * s_Dp[i];   // D skip term
                }
                sr[tid] = r;
            }
            float Bv[16], Cv[16];
#pragma unroll
            for (int n = 0; n < 16; n++) {
                Bv[n] = xc[0] * s_xpw[1 + n]  + xc[1] * s_xpw[34 + n];
                Cv[n] = xc[0] * s_xpw[17 + n] + xc[1] * s_xpw[50 + n];
            }
#pragma unroll
            for (int i = 0; i < 2; i++) {
#pragma unroll
                for (int n = 0; n < 16; n++) {
                    const int ln = i * 16 + n;
                    sa[tid * 33 + ln] = __expf(dtv[i] * s_An[ln]);     // dA
                    sb[tid * 33 + ln] = g2[i] * Bv[n];                 // dt*B*u
                    if (PASS2) sc[tid * 33 + ln] = w2[i] * Cv[n];      // gated C
                }
            }
        }
        __syncthreads();

        // ---- phase B: serial scan (warp 0, lane = state) ----
        if (tid < 32) {
            const int lane = tid;
            for (int j = 0; j < tn; j++) {
                float a  = sa[j * 33 + lane];
                float bb = sb[j * 33 + lane];
                h = fmaf(a, h, bb);
                if (PASS2) sc[j * 33 + lane] *= h;   // in-place: gatedC * h
                else       P *= a;
            }
        }
        __syncthreads();

        // ---- phase C: deferred reduction + write ----
        if (PASS2 && tid < tn) {
            float s = sr[tid];
#pragma unroll
            for (int k = 0; k < 32; k++) s += sc[tid * 33 + k];
            const int l  = tb + tid;
            const int ot = d ? (T_LEN - 1 - l) : l;   // back to original time
            g_final[(d * BATCH + b) * T_LEN + ot] = s;
        }
        __syncthreads();
    }

    if (!PASS2 && tid < 32) {
        const int idx = (chain * NCHUNK + chunk) * NST + tid;
        g_hend [idx] = h;
        g_aprod[idx] = P;
    }
}

// ---------------- kernel 3: combine chunk summaries ----------------
__global__ void combine_kernel() {
    const int chain = blockIdx.x;
    const int lane  = threadIdx.x;
    float h = 0.0f;
#pragma unroll
    for (int c = 0; c < NCHUNK; c++) {
        const int idx = (chain * NCHUNK + c) * NST + lane;
        g_hinit[idx] = h;
        h = fmaf(g_aprod[idx], h, g_hend[idx]);
    }
}

// ---------------- kernel 5: MLP + transposed gamma/beta write ----------------
// grid = (105 t-tiles, 64 batches), 256 threads = 256 output channels.
__global__ __launch_bounds__(256) void out_kernel(
    const float* __restrict__ mw,   // (2,256)
    const float* __restrict__ mb,   // (256)
    float* __restrict__ out)
{
    __shared__ __align__(16) float shf[TR];
    __shared__ __align__(16) float shb[TR];
    const int b   = blockIdx.y;
    const int t0  = blockIdx.x * TR;
    const int tid = threadIdx.x;

    if (tid < TR)           shf[tid]      = g_final[b * T_LEN + t0 + tid];
    else if (tid < 2 * TR)  shb[tid - TR] = g_final[(BATCH + b) * T_LEN + t0 + (tid - TR)];
    __syncthreads();

    const int c = tid;
    const float wf = mw[c], wb = mw[NCH + c], bias = mb[c];
    long base;
    if (c < 128) base = ((long)b * 128 + c) * T_LEN;                                     // gamma
    else         base = (long)BATCH * 128 * T_LEN + ((long)b * 128 + (c - 128)) * T_LEN; // beta
    float4* o4 = (float4*)(out + base + t0);

#pragma unroll
    for (int q = 0; q < TR / 4; q++) {
        float4 f = *(const float4*)&shf[q * 4];
        float4 g = *(const float4*)&shb[q * 4];
        float4 r;
        r.x = fmaf(f.x, wf, fmaf(g.x, wb, bias));
        r.y = fmaf(f.y, wf, fmaf(g.y, wb, bias));
        r.z = fmaf(f.z, wf, fmaf(g.z, wb, bias));
        r.w = fmaf(f.w, wf, fmaf(g.w, wb, bias));
        o4[q] = r;
    }
}

// ---------------- launch ----------------
extern "C" void kernel_launch(void* const* d_in, const int* in_sizes, int n_in,
                              void* d_out, int out_size) {
    const float* x    = (const float*)d_in[0];
    const float* in_w = (const float*)d_in[1];
    const float* cw   = (const float*)d_in[2];
    const float* cb   = (const float*)d_in[3];
    const float* xpw  = (const float*)d_in[4];
    const float* dtw  = (const float*)d_in[5];
    const float* dtb  = (const float*)d_in[6];
    const float* alog = (const float*)d_in[7];
    const float* dssm = (const float*)d_in[8];
    const float* ow   = (const float*)d_in[9];
    const float* mw   = (const float*)d_in[10];
    const float* mb   = (const float*)d_in[11];
    float* out = (float*)d_out;

    pool_kernel<<<(BATCH * T_LEN + 255) / 256, 256>>>(x);

    dim3 sg(NCHUNK, 128);
    scan_kernel<false><<<sg, TILE>>>(in_w, cw, cb, xpw, dtw, dtb, alog, dssm, ow);
    combine_kernel<<<128, 32>>>();
    scan_kernel<true ><<<sg, TILE>>>(in_w, cw, cb, xpw, dtw, dtb, alog, dssm, ow);

    out_kernel<<<dim3(T_LEN / TR, BATCH), 256>>>(mw, mb, out);
}

// round 5
// speedup vs baseline: 2.1483x; 2.1483x over previous
#include <cuda_runtime.h>
#include <math.h>

// ---------------- problem constants ----------------
#define T_LEN  8820     // BLOCK_NUM
#define BATCH  64
#define POOLW  10
#define TILE   64
#define CHUNK  256                                  // padded, multiple of TILE
#define NCHUNK 35                                   // 34*256=8704; last chunk 116 real steps
#define NTILES (CHUNK / TILE)                       // 4
#define NST    32       // d_inner(2) * d_state(16)
#define NCH    256      // mlp output channels
#define OTT    1024     // t-floats per out-kernel block

// ---------------- device scratch (no allocations allowed) ----------------
__device__ float g_pooled[BATCH * T_LEN];
__device__ float g_final [2 * BATCH * T_LEN];       // [dir][b][t] (original time)
__device__ float g_hend  [128 * NCHUNK * NST];
__device__ float g_aprod [128 * NCHUNK * NST];
__device__ float g_hinit [128 * NCHUNK * NST];

// ---------------- helpers ----------------
__device__ __forceinline__ float siluf(float x) {
    return __fdividef(x, 1.0f + __expf(-x));
}
__device__ __forceinline__ float softplusf(float x) {
    return (x > 20.0f) ? x : log1pf(__expf(x));
}

// ---------------- kernel 1: max pool ----------------
__global__ __launch_bounds__(256) void pool_kernel(const float* __restrict__ x) {
    int idx = blockIdx.x * blockDim.x + threadIdx.x;
    if (idx >= BATCH * T_LEN) return;
    const float* p = x + (long)idx * POOLW;
    float m = p[0];
#pragma unroll
    for (int j = 1; j < POOLW; j++) m = fmaxf(m, p[j]);
    g_pooled[idx] = m;
}

// ---------------- kernels 2/4: chunked selective scan ----------------
// grid = (NCHUNK, 128 chains), block = TILE threads.
// Phase A (all threads): per-timestep (a,b) pairs (+ gated-C in pass2) -> smem;
//                        padded steps get (1,0) so phase B is a fixed 64-step unroll.
// Phase B (warp 0):      h = a*h + b, lane = state; pass2 stores h over the dead b slot.
// Phase C (pass2):       y_t = r_t + sum_n sc[t][n] * h[t][n] -> g_final.
// Pass1 state product:   P = exp(A_n * sum_t dt) computed once per chunk (no serial mul).
template <bool PASS2>
__global__ __launch_bounds__(TILE) void scan_kernel(
    const float* __restrict__ in_w,  // (2,1,4)
    const float* __restrict__ cw,    // (2,2,4)
    const float* __restrict__ cb,    // (2,2)
    const float* __restrict__ xpw,   // (2,2,33)
    const float* __restrict__ dtw,   // (2,1,2)
    const float* __restrict__ dtb,   // (2,2)
    const float* __restrict__ alog,  // (2,2,16)
    const float* __restrict__ dssm,  // (2,2)
    const float* __restrict__ ow)    // (2,2,1)
{
    __shared__ float2 sab[TILE * 33];                 // (a,b) per (t, state); b slot reused for h
    __shared__ float  sc [PASS2 ? TILE * 33 : 1];     // gated C (pass2 only)
    __shared__ float  sr [PASS2 ? TILE : 1];          // residual + D term (pass2 only)
    __shared__ float  sdt[PASS2 ? 1 : TILE * 2];      // per-thread dt sums (pass1 only)
    __shared__ float s_inwx[2], s_inwz[2], s_cw[8], s_cb[2];
    __shared__ float s_xpw[66], s_dtw[2], s_dtb[2], s_An[32], s_Dp[2], s_ow[2];

    const int chain = blockIdx.y;
    const int d = chain >> 6, b = chain & 63;
    const int chunk = blockIdx.x;
    const int c0 = chunk * CHUNK;
    const int c1 = min(T_LEN, c0 + CHUNK);
    const int tid = threadIdx.x;

    if (tid < 2) {
        s_inwx[tid] = in_w[d * 4 + tid];
        s_inwz[tid] = in_w[d * 4 + 2 + tid];
        s_cb[tid]   = cb [d * 2 + tid];
        s_dtw[tid]  = dtw[d * 2 + tid];
        s_dtb[tid]  = dtb[d * 2 + tid];
        s_Dp[tid]   = dssm[d * 2 + tid];
        s_ow[tid]   = ow [d * 2 + tid];
    }
    if (tid < 8)  s_cw[tid] = cw[d * 8 + tid];
    if (tid < 32) s_An[tid] = -__expf(alog[d * 32 + tid]);   // A = -exp(A_log)
    for (int k = tid; k < 66; k += TILE) s_xpw[k] = xpw[d * 66 + k];
    __syncthreads();

    float h = 0.0f;
    float dta0 = 0.0f, dta1 = 0.0f;                   // pass1: sum of dt over this thread's steps
    if constexpr (PASS2) {
        if (tid < 32) h = g_hinit[(chain * NCHUNK + chunk) * NST + tid];
    }

#pragma unroll 1
    for (int tt = 0; tt < NTILES; ++tt) {
        const int tb = c0 + tt * TILE;
        const int l  = tb + tid;                      // position in direction frame

        // ---- phase A: parallel per-timestep precompute ----
        if (l < c1) {
            float u[4];
#pragma unroll
            for (int k = 0; k < 4; k++) {
                int lk = l - 3 + k;
                u[k] = (lk >= 0) ? g_pooled[b * T_LEN + (d ? (T_LEN - 1 - lk) : lk)] : 0.0f;
            }
            float xc[2], dtv[2], g2[2], w2[2];
#pragma unroll
            for (int i = 0; i < 2; i++) {
                float cv = s_cw[i * 4 + 0] * u[0] + s_cw[i * 4 + 1] * u[1]
                         + s_cw[i * 4 + 2] * u[2] + s_cw[i * 4 + 3] * u[3];
                cv = s_cb[i] + s_inwx[i] * cv;        // conv folded through in_proj
                xc[i] = siluf(cv);
            }
            float dtr = xc[0] * s_xpw[0] + xc[1] * s_xpw[33];
#pragma unroll
            for (int i = 0; i < 2; i++) {
                dtv[i] = softplusf(dtr * s_dtw[i] + s_dtb[i]);
                g2[i]  = dtv[i] * xc[i];
            }
            if constexpr (!PASS2) { dta0 += dtv[0]; dta1 += dtv[1]; }
            if constexpr (PASS2) {
                float r = u[3];                       // residual (pooled value)
#pragma unroll
                for (int i = 0; i < 2; i++) {
                    float z = u[3] * s_inwz[i];
                    w2[i] = siluf(z) * s_ow[i];       // gate * out_proj weight
                    r += w2[i] * xc[i] * s_Dp[i];     // D skip term
                }
                sr[tid] = r;
            }
            float Bv[16], Cv[16];
#pragma unroll
            for (int n = 0; n < 16; n++) {
                Bv[n] = xc[0] * s_xpw[1 + n]  + xc[1] * s_xpw[34 + n];
                Cv[n] = xc[0] * s_xpw[17 + n] + xc[1] * s_xpw[50 + n];
            }
#pragma unroll
            for (int i = 0; i < 2; i++) {
#pragma unroll
                for (int n = 0; n < 16; n++) {
                    const int ln = i * 16 + n;
                    sab[tid * 33 + ln] = make_float2(__expf(dtv[i] * s_An[ln]),  // dA
                                                     g2[i] * Bv[n]);             // dt*B*u
                    if constexpr (PASS2) sc[tid * 33 + ln] = w2[i] * Cv[n];      // gated C
                }
            }
        } else {
            // padded step: identity transition
#pragma unroll
            for (int ln = 0; ln < 32; ln++) {
                sab[tid * 33 + ln] = make_float2(1.0f, 0.0f);
                if constexpr (PASS2) sc[tid * 33 + ln] = 0.0f;
            }
        }
        __syncthreads();

        // ---- phase B: serial scan (warp 0, lane = state), fixed 64-step unroll ----
        if (tid < 32) {
#pragma unroll
            for (int j = 0; j < TILE; j++) {
                float2 ab = sab[j * 33 + tid];
                h = fmaf(ab.x, h, ab.y);
                if constexpr (PASS2) sab[j * 33 + tid].y = h;   // overwrite dead b slot with h
            }
        }
        __syncthreads();

        // ---- phase C: deferred reduction + write ----
        if constexpr (PASS2) {
            if (l < c1) {
                float s = sr[tid];
#pragma unroll
                for (int k = 0; k < 32; k++) s += sc[tid * 33 + k] * sab[tid * 33 + k].y;
                const int ot = d ? (T_LEN - 1 - l) : l;   // back to original time
                g_final[(d * BATCH + b) * T_LEN + ot] = s;
            }
            __syncthreads();
        }
    }

    if constexpr (!PASS2) {
        sdt[tid * 2 + 0] = dta0;
        sdt[tid * 2 + 1] = dta1;
        __syncthreads();
        if (tid < 32) {
            const int i = tid >> 4;                    // inner-channel of this state
            float S = 0.0f;
#pragma unroll
            for (int t = 0; t < TILE; t++) S += sdt[t * 2 + i];
            const int idx = (chain * NCHUNK + chunk) * NST + tid;
            g_aprod[idx] = __expf(s_An[tid] * S);      // prod_t exp(dt*A) = exp(A*sum dt)
            g_hend [idx] = h;
        }
    }
}

// ---------------- kernel 3: combine chunk summaries ----------------
__global__ void combine_kernel() {
    const int chain = blockIdx.x;
    const int lane  = threadIdx.x;
    float h = 0.0f;
#pragma unroll
    for (int c = 0; c < NCHUNK; c++) {
        const int idx = (chain * NCHUNK + c) * NST + lane;
        g_hinit[idx] = h;
        h = fmaf(g_aprod[idx], h, g_hend[idx]);
    }
}

// ---------------- kernel 5: MLP + transposed gamma/beta write ----------------
// grid = (9 t-tiles, 64 batches), 256 threads. Each thread holds one float4 of
// f/g in registers and loops over all 256 channels; warp lanes write 512B
// contiguous runs of the SAME output row -> fully coalesced STG.128.
__global__ __launch_bounds__(256) void out_kernel(
    const float* __restrict__ mw,   // (2,256)
    const float* __restrict__ mb,   // (256)
    float* __restrict__ out)
{
    __shared__ float swf[NCH], swb[NCH], sbs[NCH];
    const int b   = blockIdx.y;
    const int t0  = blockIdx.x * OTT;
    const int tid = threadIdx.x;

    swf[tid] = mw[tid];
    swb[tid] = mw[NCH + tid];
    sbs[tid] = mb[tid];

    const int t = t0 + tid * 4;
    const bool valid = (t < T_LEN);                  // T_LEN % 4 == 0, exact tail
    float4 f = make_float4(0.f, 0.f, 0.f, 0.f), g = f;
    if (valid) {
        f = *(const float4*)(g_final + (long)b * T_LEN + t);
        g = *(const float4*)(g_final + (long)(BATCH + b) * T_LEN + t);
    }
    __syncthreads();
    if (!valid) return;                              // weights staged; tail threads done

#pragma unroll 4
    for (int j = 0; j < NCH; ++j) {
        const float wf = swf[j], wb = swb[j], bias = sbs[j];
        const long row = ((j >> 7) ? (long)BATCH * 128 : 0L) + (long)b * 128 + (j & 127);
        float4 r;
        r.x = fmaf(f.x, wf, fmaf(g.x, wb, bias));
        r.y = fmaf(f.y, wf, fmaf(g.y, wb, bias));
        r.z = fmaf(f.z, wf, fmaf(g.z, wb, bias));
        r.w = fmaf(f.w, wf, fmaf(g.w, wb, bias));
        *(float4*)(out + row * T_LEN + t) = r;
    }
}

// ---------------- launch ----------------
extern "C" void kernel_launch(void* const* d_in, const int* in_sizes, int n_in,
                              void* d_out, int out_size) {
    const float* x    = (const float*)d_in[0];
    const float* in_w = (const float*)d_in[1];
    const float* cw   = (const float*)d_in[2];
    const float* cb   = (const float*)d_in[3];
    const float* xpw  = (const float*)d_in[4];
    const float* dtw  = (const float*)d_in[5];
    const float* dtb  = (const float*)d_in[6];
    const float* alog = (const float*)d_in[7];
    const float* dssm = (const float*)d_in[8];
    const float* ow   = (const float*)d_in[9];
    const float* mw   = (const float*)d_in[10];
    const float* mb   = (const float*)d_in[11];
    float* out = (float*)d_out;

    pool_kernel<<<(BATCH * T_LEN + 255) / 256, 256>>>(x);

    dim3 sg(NCHUNK, 128);
    scan_kernel<false><<<sg, TILE>>>(in_w, cw, cb, xpw, dtw, dtb, alog, dssm, ow);
    combine_kernel<<<128, 32>>>();
    scan_kernel<true ><<<sg, TILE>>>(in_w, cw, cb, xpw, dtw, dtb, alog, dssm, ow);

    out_kernel<<<dim3((T_LEN + OTT - 1) / OTT, BATCH), 256>>>(mw, mb, out);
}